// round 2
// baseline (speedup 1.0000x reference)
#include <cuda_runtime.h>
#include <math.h>

#define BB 32
#define NN 2048
#define MM 2048
#define TPB 128
#define BPB 16                 // blocks per batch
#define NBLK (BB * BPB)        // 512 total blocks (co-resident: 4/SM * 148 = 592)
#define PAIRS (MM / 2)
#define LOG2E 1.4426950408889634f

// Cross-block scratch (no allocations allowed)
__device__ float    g_T[BB * 4];          // per-batch transform: c, s, tx, ty
__device__ float    g_part[NBLK * 8];     // per-block partial sums
__device__ unsigned g_ctr = 0;            // monotonic arrival counter (survives replays)
__device__ unsigned g_gen = 0;            // monotonic generation counter

typedef unsigned long long ull;

__device__ __forceinline__ ull pk(float a, float b) {
    ull r; asm("mov.b64 %0,{%1,%2};" : "=l"(r) : "f"(a), "f"(b)); return r;
}
__device__ __forceinline__ void upk(ull v, float& a, float& b) {
    asm("mov.b64 {%0,%1},%2;" : "=f"(a), "=f"(b) : "l"(v));
}
__device__ __forceinline__ ull fma2(ull a, ull b, ull c) {
    ull r; asm("fma.rn.f32x2 %0,%1,%2,%3;" : "=l"(r) : "l"(a), "l"(b), "l"(c)); return r;
}
__device__ __forceinline__ ull add2(ull a, ull b) {
    ull r; asm("add.rn.f32x2 %0,%1,%2;" : "=l"(r) : "l"(a), "l"(b)); return r;
}
__device__ __forceinline__ float ex2(float x) {
    float y; asm("ex2.approx.ftz.f32 %0,%1;" : "=f"(y) : "f"(x)); return y;
}

__global__ __launch_bounds__(TPB, 4)
void icp_persistent_kernel(const float* __restrict__ source,
                           const float* __restrict__ target,
                           const float* __restrict__ init,
                           float* __restrict__ out) {
    __shared__ float4 smA[PAIRS];   // (tx0, tx1, ty0, ty1) per target pair — 16KB
    __shared__ float2 smC[PAIRS];   // (c0, c1) = -log2e*|t|^2 per pair      — 8KB
    __shared__ float  red[4][8];
    __shared__ unsigned s_last;

    const int tid = threadIdx.x;
    const int b   = blockIdx.x >> 4;
    const int blk = blockIdx.x & 15;

    // Generation base for this replay: read before any barrier arrival in any
    // block, so it is the pre-replay value (first gen increment requires ALL
    // blocks to have arrived at iter-0 barrier, which is after this read).
    unsigned base = 0;
    if (tid == 0) { volatile unsigned* vg = &g_gen; base = *vg; }

    // ---- Load + transform target tile into smem (packed-pair layout) ----
    const float4* tg = (const float4*)(target + (size_t)b * MM * 2);
#pragma unroll
    for (int i = 0; i < PAIRS / TPB; i++) {
        int p = tid + i * TPB;
        float4 q = tg[p];                       // tx0, ty0, tx1, ty1
        smA[p] = make_float4(q.x, q.z, q.y, q.w);
        smC[p] = make_float2(-LOG2E * (q.x * q.x + q.y * q.y),
                             -LOG2E * (q.z * q.z + q.w * q.w));
    }

    // ---- Per-thread source row, initial transform ----
    const int row = blk * TPB + tid;
    const float2 s2 = ((const float2*)source)[b * NN + row];

    float th = init[b * 3 + 0];
    float Tc = cosf(th), Ts = sinf(th);
    float Tx = init[b * 3 + 1], Ty = init[b * 3 + 2];

    // Publish initial T so the updater block can read it (one writer per batch).
    if (blk == 0 && tid == 0) {
        volatile float* vT = g_T;
        vT[b * 4 + 0] = Tc; vT[b * 4 + 1] = Ts;
        vT[b * 4 + 2] = Tx; vT[b * 4 + 3] = Ty;
        __threadfence();
    }
    __syncthreads();

    for (int it = 0; it < 5; it++) {
        const float stx = Tc * s2.x - Ts * s2.y + Tx;
        const float sty = Ts * s2.x + Tc * s2.y + Ty;
        const float px  = 2.f * LOG2E * stx;
        const float py  = 2.f * LOG2E * sty;
        const float nbv = -LOG2E * (stx * stx + sty * sty); // exact log2 upper bound

        const ull px2 = pk(px, px), py2 = pk(py, py), nb2 = pk(nbv, nbv);
        ull sa = 0ull, axa = 0ull, aya = 0ull;

#pragma unroll 4
        for (int p = 0; p < PAIRS; p++) {
            float4 a = smA[p];
            float2 c = smC[p];
            ull tx = pk(a.x, a.y);
            ull ty = pk(a.z, a.w);
            ull cc = pk(c.x, c.y);
            ull l  = add2(fma2(px2, tx, fma2(py2, ty, cc)), nb2);
            float l0, l1; upk(l, l0, l1);
            ull e  = pk(ex2(l0), ex2(l1));
            sa  = add2(sa, e);
            axa = fma2(e, tx, axa);
            aya = fma2(e, ty, aya);
        }

        float sl, sh, axl, axh, ayl, ayh;
        upk(sa, sl, sh); upk(axa, axl, axh); upk(aya, ayl, ayh);
        const float sum = sl + sh;
        const float inv = 1.0f / sum;
        const float tcx = (axl + axh) * inv;
        const float tcy = (ayl + ayh) * inv;

        // ---- 8-term block reduction ----
        float v[8];
        v[0] = stx;       v[1] = sty;
        v[2] = tcx;       v[3] = tcy;
        v[4] = stx * tcx; v[5] = stx * tcy;
        v[6] = sty * tcx; v[7] = sty * tcy;
#pragma unroll
        for (int off = 16; off > 0; off >>= 1)
#pragma unroll
            for (int k = 0; k < 8; k++)
                v[k] += __shfl_down_sync(0xffffffffu, v[k], off);
        const int wid = tid >> 5, lane = tid & 31;
        if (lane == 0)
#pragma unroll
            for (int k = 0; k < 8; k++) red[wid][k] = v[k];
        __syncthreads();
        if (tid < 8) {
            float r = (red[0][tid] + red[1][tid]) + (red[2][tid] + red[3][tid]);
            g_part[(b * BPB + blk) * 8 + tid] = r;
            __threadfence();
        }
        __syncthreads();

        // ---- Grid barrier: last-arriving block performs the update ----
        if (tid == 0) {
            unsigned d = atomicAdd(&g_ctr, 1u) + 1u;
            s_last = ((d % NBLK) == 0u) ? 1u : 0u;
        }
        __syncthreads();

        if (s_last) {
            if (tid < BB) {
                const int bb = tid;
                __threadfence();
                volatile float* vp = g_part;
                double S[8];
#pragma unroll
                for (int k = 0; k < 8; k++) S[k] = 0.0;
                for (int j = 0; j < BPB; j++)
#pragma unroll
                    for (int k = 0; k < 8; k++)
                        S[k] += (double)vp[(bb * BPB + j) * 8 + k];

                const double n   = (double)NN;
                const double csx = S[0] / n, csy = S[1] / n;
                const double ctx = S[2] / n, cty = S[3] / n;
                const double H00 = S[4] - S[0] * S[2] / n;
                const double H01 = S[5] - S[0] * S[3] / n;
                const double H10 = S[6] - S[1] * S[2] / n;
                const double H11 = S[7] - S[1] * S[3] / n;

                // Polar factor of H^T (== V U^T incl. reflection case)
                const double b0 = H00 + H11, b1 = H10 - H01;
                const double c0 = H00 - H11, c1 = H10 + H01;
                double R00, R01, R10, R11;
                if (b0 * b0 + b1 * b1 >= c0 * c0 + c1 * c1) {
                    double h = sqrt(b0 * b0 + b1 * b1);
                    double ih = (h > 0.0) ? 1.0 / h : 0.0;
                    R00 = b0 * ih;  R01 = b1 * ih;
                    R10 = -b1 * ih; R11 = b0 * ih;
                } else {
                    double h = sqrt(c0 * c0 + c1 * c1);
                    double ih = (h > 0.0) ? 1.0 / h : 0.0;
                    R00 = c0 * ih;  R01 = c1 * ih;
                    R10 = c1 * ih;  R11 = -c0 * ih;
                }
                const double tdx = ctx - (R00 * csx + R01 * csy);
                const double tdy = cty - (R10 * csx + R11 * csy);
                double nn2 = sqrt(R00 * R00 + R10 * R10);
                double inh = (nn2 > 0.0) ? 1.0 / nn2 : 0.0;
                const double cd = R00 * inh, sd = R10 * inh;

                volatile float* vT = g_T;
                const double oc = (double)vT[bb * 4 + 0];
                const double os = (double)vT[bb * 4 + 1];
                const double ox = (double)vT[bb * 4 + 2];
                const double oy = (double)vT[bb * 4 + 3];
                const float nc  = (float)(cd * oc - sd * os);
                const float ns  = (float)(sd * oc + cd * os);
                const float ntx = (float)(cd * ox - sd * oy + tdx);
                const float nty = (float)(sd * ox + cd * oy + tdy);
                vT[bb * 4 + 0] = nc;  vT[bb * 4 + 1] = ns;
                vT[bb * 4 + 2] = ntx; vT[bb * 4 + 3] = nty;
                if (it == 4) {
                    out[bb * 3 + 0] = atan2f(ns, nc);
                    out[bb * 3 + 1] = ntx;
                    out[bb * 3 + 2] = nty;
                }
            }
            __syncthreads();
            if (tid == 0) { __threadfence(); atomicAdd(&g_gen, 1u); }
        }

        if (it < 4) {
            if (tid == 0) {
                volatile unsigned* vg = &g_gen;
                while (*vg < base + (unsigned)it + 1u) __nanosleep(64);
            }
            __syncthreads();
            volatile float* vT = g_T;   // volatile: bypass L1, read updated T
            Tc = vT[b * 4 + 0]; Ts = vT[b * 4 + 1];
            Tx = vT[b * 4 + 2]; Ty = vT[b * 4 + 3];
        }
    }
}

extern "C" void kernel_launch(void* const* d_in, const int* in_sizes, int n_in,
                              void* d_out, int out_size) {
    const float* source = (const float*)d_in[0];
    const float* target = (const float*)d_in[1];
    const float* init   = (const float*)d_in[2];
    float* out = (float*)d_out;

    icp_persistent_kernel<<<NBLK, TPB>>>(source, target, init, out);
}

// round 3
// speedup vs baseline: 1.4284x; 1.4284x over previous
#include <cuda_runtime.h>
#include <math.h>

#define BB 32
#define NN 2048
#define MM 2048
#define TPB 64
#define BPB (NN / TPB)         // 32 blocks per batch
#define NBLK (BB * BPB)        // 1024 blocks; 7/SM co-resident -> single wave
#define LOG2E 1.4426950408889634f
#define CSHIFT 64.0f           // global log2-domain shift (cancels in ratios)

// Scratch (no allocations allowed)
__device__ float g_T[BB * 4];           // per-batch transform: c, s, tx, ty
__device__ float g_part[NBLK * 8];      // per-block partial sums

__device__ __forceinline__ float ex2(float x) {
    float y;
    asm("ex2.approx.ftz.f32 %0, %1;" : "=f"(y) : "f"(x));
    return y;
}

// ---------------------------------------------------------------------------
// Fused iteration. grid = 1024 (1D), block = 64. One source row per thread.
// smem: 24KB/block -> up to 9 blocks/SM; 1024/148 = 6.92 -> single wave.
// ---------------------------------------------------------------------------
__global__ __launch_bounds__(TPB, 7)
void iter_kernel(const float* __restrict__ source,
                 const float* __restrict__ target,
                 const float* __restrict__ init,
                 int it) {
    __shared__ float2 smT[MM];     // 16 KB: (tx, ty)
    __shared__ float  smC[MM];     //  8 KB: -log2e*|t|^2 - CSHIFT
    __shared__ float  red[2][8];

    const int tid = threadIdx.x;
    const int b   = blockIdx.x >> 5;
    const int blk = blockIdx.x & 31;

    // ---- smem fill: raw target -> packed coefficients (prep folded in) ----
    const float4* tg = (const float4*)(target + (size_t)b * MM * 2);
#pragma unroll
    for (int i = 0; i < MM / 2 / TPB; i++) {   // 16 iterations, 2 points each
        int p = tid + i * TPB;
        float4 q = tg[p];                      // tx0, ty0, tx1, ty1
        smT[2 * p + 0] = make_float2(q.x, q.y);
        smT[2 * p + 1] = make_float2(q.z, q.w);
        smC[2 * p + 0] = fmaf(-LOG2E, q.x * q.x + q.y * q.y, -CSHIFT);
        smC[2 * p + 1] = fmaf(-LOG2E, q.z * q.z + q.w * q.w, -CSHIFT);
    }

    // ---- transform for this iteration ----
    float Tc, Ts, Tx, Ty;
    if (it == 0) {
        float th = init[b * 3 + 0];
        Tc = cosf(th); Ts = sinf(th);
        Tx = init[b * 3 + 1]; Ty = init[b * 3 + 2];
    } else {
        Tc = g_T[b * 4 + 0]; Ts = g_T[b * 4 + 1];
        Tx = g_T[b * 4 + 2]; Ty = g_T[b * 4 + 3];
    }

    const int row = blk * TPB + tid;
    const float2 s2 = ((const float2*)source)[b * NN + row];
    const float stx = Tc * s2.x - Ts * s2.y + Tx;
    const float sty = Ts * s2.x + Tc * s2.y + Ty;
    const float px  = 2.f * LOG2E * stx;
    const float py  = 2.f * LOG2E * sty;

    __syncthreads();

    // ---- mainloop: 5 fma-pipe ops + 1 MUFU per element ----
    float s0 = 0.f, s1 = 0.f;
    float ax0 = 0.f, ax1 = 0.f;
    float ay0 = 0.f, ay1 = 0.f;

#pragma unroll 8
    for (int m = 0; m < MM; m += 2) {
        float2 t0 = smT[m + 0];
        float2 t1 = smT[m + 1];
        float  c0 = smC[m + 0];
        float  c1 = smC[m + 1];
        float e0 = ex2(fmaf(px, t0.x, fmaf(py, t0.y, c0)));
        float e1 = ex2(fmaf(px, t1.x, fmaf(py, t1.y, c1)));
        s0 += e0; ax0 = fmaf(e0, t0.x, ax0); ay0 = fmaf(e0, t0.y, ay0);
        s1 += e1; ax1 = fmaf(e1, t1.x, ax1); ay1 = fmaf(e1, t1.y, ay1);
    }

    const float inv = 1.0f / (s0 + s1);
    const float tcx = (ax0 + ax1) * inv;
    const float tcy = (ay0 + ay1) * inv;

    // ---- 8-term block reduction ----
    float v[8];
    v[0] = stx;       v[1] = sty;
    v[2] = tcx;       v[3] = tcy;
    v[4] = stx * tcx; v[5] = stx * tcy;
    v[6] = sty * tcx; v[7] = sty * tcy;
#pragma unroll
    for (int off = 16; off > 0; off >>= 1)
#pragma unroll
        for (int k = 0; k < 8; k++)
            v[k] += __shfl_down_sync(0xffffffffu, v[k], off);
    const int wid = tid >> 5, lane = tid & 31;
    if (lane == 0)
#pragma unroll
        for (int k = 0; k < 8; k++) red[wid][k] = v[k];
    __syncthreads();
    if (tid < 8)
        g_part[(b * BPB + blk) * 8 + tid] = red[0][tid] + red[1][tid];
}

// ---------------------------------------------------------------------------
// Update: combine partials (fixed order, double), Kabsch via polar factor of
// H^T (== V U^T of the SVD incl. reflection case), compose transform.
// ---------------------------------------------------------------------------
__global__ void update_kernel(const float* __restrict__ init,
                              float* __restrict__ out, int it) {
    int b = threadIdx.x;
    if (b >= BB) return;

    double S[8];
#pragma unroll
    for (int k = 0; k < 8; k++) S[k] = 0.0;
#pragma unroll 4
    for (int blk = 0; blk < BPB; blk++)
#pragma unroll
        for (int k = 0; k < 8; k++)
            S[k] += (double)g_part[(b * BPB + blk) * 8 + k];

    const double n   = (double)NN;
    const double csx = S[0] / n, csy = S[1] / n;
    const double ctx = S[2] / n, cty = S[3] / n;
    const double H00 = S[4] - S[0] * S[2] / n;
    const double H01 = S[5] - S[0] * S[3] / n;
    const double H10 = S[6] - S[1] * S[2] / n;
    const double H11 = S[7] - S[1] * S[3] / n;

    // Polar factor of A = H^T: rotation part vs reflection part.
    const double b0 = H00 + H11, b1 = H10 - H01;
    const double c0 = H00 - H11, c1 = H10 + H01;
    double R00, R01, R10, R11;
    if (b0 * b0 + b1 * b1 >= c0 * c0 + c1 * c1) {
        double h = sqrt(b0 * b0 + b1 * b1);
        double ih = (h > 0.0) ? 1.0 / h : 0.0;
        R00 = b0 * ih;  R01 = b1 * ih;
        R10 = -b1 * ih; R11 = b0 * ih;
    } else {
        double h = sqrt(c0 * c0 + c1 * c1);
        double ih = (h > 0.0) ? 1.0 / h : 0.0;
        R00 = c0 * ih;  R01 = c1 * ih;
        R10 = c1 * ih;  R11 = -c0 * ih;
    }
    const double tdx = ctx - (R00 * csx + R01 * csy);
    const double tdy = cty - (R10 * csx + R11 * csy);

    // Applied delta rotation = normalize(R00, R10) (matches vec2mat(atan2)).
    double nn2 = sqrt(R00 * R00 + R10 * R10);
    double inh = (nn2 > 0.0) ? 1.0 / nn2 : 0.0;
    const double cd = R00 * inh, sd = R10 * inh;

    double oc, os, ox, oy;
    if (it == 0) {
        float th = init[b * 3 + 0];
        oc = (double)cosf(th); os = (double)sinf(th);
        ox = (double)init[b * 3 + 1]; oy = (double)init[b * 3 + 2];
    } else {
        oc = (double)g_T[b * 4 + 0]; os = (double)g_T[b * 4 + 1];
        ox = (double)g_T[b * 4 + 2]; oy = (double)g_T[b * 4 + 3];
    }

    const float nc  = (float)(cd * oc - sd * os);
    const float ns  = (float)(sd * oc + cd * os);
    const float ntx = (float)(cd * ox - sd * oy + tdx);
    const float nty = (float)(sd * ox + cd * oy + tdy);

    g_T[b * 4 + 0] = nc;  g_T[b * 4 + 1] = ns;
    g_T[b * 4 + 2] = ntx; g_T[b * 4 + 3] = nty;

    if (it == 4) {
        out[b * 3 + 0] = atan2f(ns, nc);
        out[b * 3 + 1] = ntx;
        out[b * 3 + 2] = nty;
    }
}

// ---------------------------------------------------------------------------
extern "C" void kernel_launch(void* const* d_in, const int* in_sizes, int n_in,
                              void* d_out, int out_size) {
    const float* source = (const float*)d_in[0];
    const float* target = (const float*)d_in[1];
    const float* init   = (const float*)d_in[2];
    float* out = (float*)d_out;

    for (int it = 0; it < 5; it++) {
        iter_kernel<<<NBLK, TPB>>>(source, target, init, it);
        update_kernel<<<1, 32>>>(init, out, it);
    }
}

// round 4
// speedup vs baseline: 2.1208x; 1.4847x over previous
#include <cuda_runtime.h>
#include <math.h>

#define BB 32
#define NN 2048
#define MM 2048
#define TPB 64
#define BPB (NN / TPB)         // 32 blocks per batch
#define NBLK (BB * BPB)        // 1024 blocks; ~7/SM co-resident -> single wave
#define LOG2E 1.4426950408889634f
#define CSHIFT 64.0f           // global log2-domain shift (cancels in softmax ratio)

// Scratch (no allocations allowed)
__device__ float g_T[BB * 4];           // per-batch transform: c, s, tx, ty
__device__ float g_part[NBLK * 8];      // per-block partial sums

__device__ __forceinline__ float ex2(float x) {
    float y;
    asm("ex2.approx.ftz.f32 %0, %1;" : "=f"(y) : "f"(x));
    return y;
}

// ---------------------------------------------------------------------------
// Fused iteration (unchanged from R3 — measured ~36.7us, ~88% of FFMA ceiling).
// grid = 1024 (1D), block = 64. One source row per thread.
// ---------------------------------------------------------------------------
__global__ __launch_bounds__(TPB, 7)
void iter_kernel(const float* __restrict__ source,
                 const float* __restrict__ target,
                 const float* __restrict__ init,
                 int it) {
    __shared__ float2 smT[MM];     // 16 KB: (tx, ty)
    __shared__ float  smC[MM];     //  8 KB: -log2e*|t|^2 - CSHIFT
    __shared__ float  red[2][8];

    const int tid = threadIdx.x;
    const int b   = blockIdx.x >> 5;
    const int blk = blockIdx.x & 31;

    // ---- smem fill: raw target -> coefficients (prep folded in) ----
    const float4* tg = (const float4*)(target + (size_t)b * MM * 2);
#pragma unroll
    for (int i = 0; i < MM / 2 / TPB; i++) {   // 16 iterations, 2 points each
        int p = tid + i * TPB;
        float4 q = tg[p];                      // tx0, ty0, tx1, ty1
        smT[2 * p + 0] = make_float2(q.x, q.y);
        smT[2 * p + 1] = make_float2(q.z, q.w);
        smC[2 * p + 0] = fmaf(-LOG2E, q.x * q.x + q.y * q.y, -CSHIFT);
        smC[2 * p + 1] = fmaf(-LOG2E, q.z * q.z + q.w * q.w, -CSHIFT);
    }

    // ---- transform for this iteration ----
    float Tc, Ts, Tx, Ty;
    if (it == 0) {
        float th = init[b * 3 + 0];
        Tc = cosf(th); Ts = sinf(th);
        Tx = init[b * 3 + 1]; Ty = init[b * 3 + 2];
    } else {
        Tc = g_T[b * 4 + 0]; Ts = g_T[b * 4 + 1];
        Tx = g_T[b * 4 + 2]; Ty = g_T[b * 4 + 3];
    }

    const int row = blk * TPB + tid;
    const float2 s2 = ((const float2*)source)[b * NN + row];
    const float stx = Tc * s2.x - Ts * s2.y + Tx;
    const float sty = Ts * s2.x + Tc * s2.y + Ty;
    const float px  = 2.f * LOG2E * stx;
    const float py  = 2.f * LOG2E * sty;

    __syncthreads();

    // ---- mainloop: 5 fma-pipe ops + 1 MUFU per element ----
    float s0 = 0.f, s1 = 0.f;
    float ax0 = 0.f, ax1 = 0.f;
    float ay0 = 0.f, ay1 = 0.f;

#pragma unroll 8
    for (int m = 0; m < MM; m += 2) {
        float2 t0 = smT[m + 0];
        float2 t1 = smT[m + 1];
        float  c0 = smC[m + 0];
        float  c1 = smC[m + 1];
        float e0 = ex2(fmaf(px, t0.x, fmaf(py, t0.y, c0)));
        float e1 = ex2(fmaf(px, t1.x, fmaf(py, t1.y, c1)));
        s0 += e0; ax0 = fmaf(e0, t0.x, ax0); ay0 = fmaf(e0, t0.y, ay0);
        s1 += e1; ax1 = fmaf(e1, t1.x, ax1); ay1 = fmaf(e1, t1.y, ay1);
    }

    const float inv = 1.0f / (s0 + s1);
    const float tcx = (ax0 + ax1) * inv;
    const float tcy = (ay0 + ay1) * inv;

    // ---- 8-term block reduction ----
    float v[8];
    v[0] = stx;       v[1] = sty;
    v[2] = tcx;       v[3] = tcy;
    v[4] = stx * tcx; v[5] = stx * tcy;
    v[6] = sty * tcx; v[7] = sty * tcy;
#pragma unroll
    for (int off = 16; off > 0; off >>= 1)
#pragma unroll
        for (int k = 0; k < 8; k++)
            v[k] += __shfl_down_sync(0xffffffffu, v[k], off);
    const int wid = tid >> 5, lane = tid & 31;
    if (lane == 0)
#pragma unroll
        for (int k = 0; k < 8; k++) red[wid][k] = v[k];
    __syncthreads();
    if (tid < 8)
        g_part[(b * BPB + blk) * 8 + tid] = red[0][tid] + red[1][tid];
}

// ---------------------------------------------------------------------------
// Update: 1 block x 1024 threads. Warp w = batch w. Lane j loads block j's 8
// partials (two coalesced float4), fixed-order shuffle tree (deterministic),
// lane 0 does the fp32 Kabsch (polar factor of H^T == V U^T incl. reflection).
// ---------------------------------------------------------------------------
__global__ __launch_bounds__(BB * 32)
void update_kernel(const float* __restrict__ init,
                   float* __restrict__ out, int it) {
    const int b    = threadIdx.x >> 5;   // batch = warp id
    const int lane = threadIdx.x & 31;   // block index within batch (BPB == 32)

    const float4* p = (const float4*)&g_part[(b * BPB + lane) * 8];
    float4 qa = p[0];
    float4 qb = p[1];
    float v[8] = {qa.x, qa.y, qa.z, qa.w, qb.x, qb.y, qb.z, qb.w};

#pragma unroll
    for (int off = 16; off > 0; off >>= 1)
#pragma unroll
        for (int k = 0; k < 8; k++)
            v[k] += __shfl_down_sync(0xffffffffu, v[k], off);

    if (lane != 0) return;

    const float n   = (float)NN;
    const float inN = 1.0f / n;
    const float csx = v[0] * inN, csy = v[1] * inN;
    const float ctx = v[2] * inN, cty = v[3] * inN;
    const float H00 = v[4] - v[0] * v[2] * inN;
    const float H01 = v[5] - v[0] * v[3] * inN;
    const float H10 = v[6] - v[1] * v[2] * inN;
    const float H11 = v[7] - v[1] * v[3] * inN;

    // Polar factor of A = H^T: rotation part vs reflection part.
    const float b0 = H00 + H11, b1 = H10 - H01;
    const float c0 = H00 - H11, c1 = H10 + H01;
    const float nb = b0 * b0 + b1 * b1;
    const float nc2 = c0 * c0 + c1 * c1;

    float R00, R01, R10, R11;
    if (nb >= nc2) {
        float ih = (nb > 0.f) ? rsqrtf(nb) : 0.f;
        R00 = b0 * ih;  R01 = b1 * ih;
        R10 = -b1 * ih; R11 = b0 * ih;
    } else {
        float ih = (nc2 > 0.f) ? rsqrtf(nc2) : 0.f;
        R00 = c0 * ih;  R01 = c1 * ih;
        R10 = c1 * ih;  R11 = -c0 * ih;
    }
    const float tdx = ctx - (R00 * csx + R01 * csy);
    const float tdy = cty - (R10 * csx + R11 * csy);

    // Applied delta rotation = normalize(R00, R10) (matches vec2mat(atan2)).
    const float nn2 = R00 * R00 + R10 * R10;
    const float inh = (nn2 > 0.f) ? rsqrtf(nn2) : 0.f;
    const float cd = R00 * inh, sd = R10 * inh;

    float oc, os, ox, oy;
    if (it == 0) {
        float th = init[b * 3 + 0];
        oc = cosf(th); os = sinf(th);
        ox = init[b * 3 + 1]; oy = init[b * 3 + 2];
    } else {
        oc = g_T[b * 4 + 0]; os = g_T[b * 4 + 1];
        ox = g_T[b * 4 + 2]; oy = g_T[b * 4 + 3];
    }

    const float nc  = cd * oc - sd * os;
    const float ns  = sd * oc + cd * os;
    const float ntx = cd * ox - sd * oy + tdx;
    const float nty = sd * ox + cd * oy + tdy;

    g_T[b * 4 + 0] = nc;  g_T[b * 4 + 1] = ns;
    g_T[b * 4 + 2] = ntx; g_T[b * 4 + 3] = nty;

    if (it == 4) {
        out[b * 3 + 0] = atan2f(ns, nc);
        out[b * 3 + 1] = ntx;
        out[b * 3 + 2] = nty;
    }
}

// ---------------------------------------------------------------------------
extern "C" void kernel_launch(void* const* d_in, const int* in_sizes, int n_in,
                              void* d_out, int out_size) {
    const float* source = (const float*)d_in[0];
    const float* target = (const float*)d_in[1];
    const float* init   = (const float*)d_in[2];
    float* out = (float*)d_out;

    for (int it = 0; it < 5; it++) {
        iter_kernel<<<NBLK, TPB>>>(source, target, init, it);
        update_kernel<<<1, BB * 32>>>(init, out, it);
    }
}